// round 6
// baseline (speedup 1.0000x reference)
#include <cuda_runtime.h>
#include <mma.h>
#include <cstdint>

using namespace nvcuda;

#define NB  16     // batch
#define MQ  512    // queries
#define NKV 2048   // keys per batch
#define DIM 1024   // embedding dim

// Scratch: qW = (query @ W) / 32, fp32
__device__ float g_qW[MQ * DIM];
// Fallback attention buffer if harness output only holds `out`
__device__ float g_att[(size_t)NB * MQ * NKV];

#define LDA 36          // 32 + 4 pad
#define LDB_NN 132      // 128 + 4 pad
#define A_STAGE (128 * LDA)
#define B_STAGE_NT (128 * LDA)
#define B_STAGE_NN (32 * LDB_NN)

// ---------------------------------------------------------------------------
// Kernel 1: qW = query @ W * (1/32), fp32 tiled SGEMM (small: ~1 GFLOP)
// ---------------------------------------------------------------------------
__global__ void qw_kernel(const float* __restrict__ query, const float* __restrict__ W) {
    __shared__ float As[16][68];
    __shared__ float Bs[16][68];
    const int m0 = blockIdx.y * 64;
    const int n0 = blockIdx.x * 64;
    const int tid = threadIdx.x;          // 256
    const int tx = tid & 15, ty = tid >> 4;

    float acc[4][4] = {};
    for (int k0 = 0; k0 < DIM; k0 += 16) {
        #pragma unroll
        for (int it = 0; it < 4; it++) {
            int e = it * 256 + tid;
            int m  = e >> 4, kk = e & 15;
            As[kk][m] = query[(size_t)(m0 + m) * DIM + k0 + kk];
            int kk2 = e >> 6, n = e & 63;
            Bs[kk2][n] = W[(size_t)(k0 + kk2) * DIM + n0 + n];
        }
        __syncthreads();
        #pragma unroll
        for (int kk = 0; kk < 16; kk++) {
            float4 a4 = *(const float4*)&As[kk][ty * 4];
            float4 b4 = *(const float4*)&Bs[kk][tx * 4];
            float a[4] = {a4.x, a4.y, a4.z, a4.w};
            float b[4] = {b4.x, b4.y, b4.z, b4.w};
            #pragma unroll
            for (int i = 0; i < 4; i++)
                #pragma unroll
                for (int j = 0; j < 4; j++)
                    acc[i][j] += a[i] * b[j];
        }
        __syncthreads();
    }
    #pragma unroll
    for (int i = 0; i < 4; i++)
        #pragma unroll
        for (int j = 0; j < 4; j++)
            g_qW[(size_t)(m0 + ty * 4 + i) * DIM + n0 + tx * 4 + j] = acc[i][j] * 0.03125f;
}

// ---------------------------------------------------------------------------
// Kernel 2: logits[b,m,n] = sum_d qW[m,d]*key[b,n,d]  (NT, tf32 wmma)
// 128x128 block tile, 256 thr (8 warps, 4x2), warp tile 32x64, BK=32,
// double-buffered smem + register-staged prefetch.
// ---------------------------------------------------------------------------
__global__ __launch_bounds__(256)
void logits_kernel(const float* __restrict__ key, float* __restrict__ att) {
    extern __shared__ float sm[];
    float* As = sm;                       // [2][128][36]
    float* Bs = sm + 2 * A_STAGE;         // [2][128][36]

    const int b  = blockIdx.z;
    const int m0 = blockIdx.y * 128;
    const int n0 = blockIdx.x * 128;
    const int tid  = threadIdx.x;
    const int warp = tid >> 5;
    const int wm = warp >> 1, wn = warp & 1;   // 4 x 2

    const float* keyb = key + (size_t)b * NKV * DIM;

    // per-thread staging coordinates: 4 float4 each for A and B
    int srow[4], scol[4];
    #pragma unroll
    for (int it = 0; it < 4; it++) {
        int idx = it * 256 + tid;
        srow[it] = idx >> 3;          // 0..127
        scol[it] = (idx & 7) * 4;     // 0..28
    }

    wmma::fragment<wmma::accumulator, 16, 16, 8, float> c[2][4];
    #pragma unroll
    for (int i = 0; i < 2; i++)
        #pragma unroll
        for (int j = 0; j < 4; j++)
            wmma::fill_fragment(c[i][j], 0.0f);

    float4 ra[4], rb[4];
    // prologue: tile 0 -> regs
    #pragma unroll
    for (int it = 0; it < 4; it++) {
        ra[it] = *(const float4*)(g_qW + (size_t)(m0 + srow[it]) * DIM + scol[it]);
        rb[it] = *(const float4*)(keyb + (size_t)(n0 + srow[it]) * DIM + scol[it]);
    }
    #pragma unroll
    for (int it = 0; it < 4; it++) {
        float4 va, vb;
        va.x = wmma::__float_to_tf32(ra[it].x); va.y = wmma::__float_to_tf32(ra[it].y);
        va.z = wmma::__float_to_tf32(ra[it].z); va.w = wmma::__float_to_tf32(ra[it].w);
        vb.x = wmma::__float_to_tf32(rb[it].x); vb.y = wmma::__float_to_tf32(rb[it].y);
        vb.z = wmma::__float_to_tf32(rb[it].z); vb.w = wmma::__float_to_tf32(rb[it].w);
        *(float4*)(As + srow[it] * LDA + scol[it]) = va;
        *(float4*)(Bs + srow[it] * LDA + scol[it]) = vb;
    }
    __syncthreads();

    const int NIT = DIM / 32;   // 32
    for (int t = 0; t < NIT; t++) {
        const int buf = t & 1;
        if (t + 1 < NIT) {
            const int k0 = (t + 1) * 32;
            #pragma unroll
            for (int it = 0; it < 4; it++) {
                ra[it] = *(const float4*)(g_qW + (size_t)(m0 + srow[it]) * DIM + k0 + scol[it]);
                rb[it] = *(const float4*)(keyb + (size_t)(n0 + srow[it]) * DIM + k0 + scol[it]);
            }
        }
        const float* Ab = As + buf * A_STAGE;
        const float* Bb = Bs + buf * B_STAGE_NT;
        #pragma unroll
        for (int kk = 0; kk < 4; kk++) {
            wmma::fragment<wmma::matrix_a, 16, 16, 8, wmma::precision::tf32, wmma::row_major> a[2];
            wmma::fragment<wmma::matrix_b, 16, 16, 8, wmma::precision::tf32, wmma::col_major> bf[4];
            #pragma unroll
            for (int i = 0; i < 2; i++)
                wmma::load_matrix_sync(a[i], Ab + (wm * 32 + i * 16) * LDA + kk * 8, LDA);
            #pragma unroll
            for (int j = 0; j < 4; j++)
                wmma::load_matrix_sync(bf[j], Bb + (wn * 64 + j * 16) * LDA + kk * 8, LDA);
            #pragma unroll
            for (int i = 0; i < 2; i++)
                #pragma unroll
                for (int j = 0; j < 4; j++)
                    wmma::mma_sync(c[i][j], a[i], bf[j], c[i][j]);
        }
        if (t + 1 < NIT) {
            float* An = As + (buf ^ 1) * A_STAGE;
            float* Bn = Bs + (buf ^ 1) * B_STAGE_NT;
            #pragma unroll
            for (int it = 0; it < 4; it++) {
                float4 va, vb;
                va.x = wmma::__float_to_tf32(ra[it].x); va.y = wmma::__float_to_tf32(ra[it].y);
                va.z = wmma::__float_to_tf32(ra[it].z); va.w = wmma::__float_to_tf32(ra[it].w);
                vb.x = wmma::__float_to_tf32(rb[it].x); vb.y = wmma::__float_to_tf32(rb[it].y);
                vb.z = wmma::__float_to_tf32(rb[it].z); vb.w = wmma::__float_to_tf32(rb[it].w);
                *(float4*)(An + srow[it] * LDA + scol[it]) = va;
                *(float4*)(Bn + srow[it] * LDA + scol[it]) = vb;
            }
        }
        __syncthreads();
    }

    #pragma unroll
    for (int i = 0; i < 2; i++)
        #pragma unroll
        for (int j = 0; j < 4; j++) {
            float* p = att + ((size_t)b * MQ + m0 + wm * 32 + i * 16) * NKV
                           + n0 + wn * 64 + j * 16;
            wmma::store_matrix_sync(p, c[i][j], NKV, wmma::mem_row_major);
        }
}

// ---------------------------------------------------------------------------
// Kernel 3: single-pass masked softmax over N per row (values in registers)
// ---------------------------------------------------------------------------
__global__ void softmax_kernel(const int* __restrict__ mask, float* __restrict__ att) {
    const size_t row = blockIdx.x;               // NB*MQ rows
    float* p = att + row * NKV;
    const int* mk = mask + row * NKV;
    const int tid = threadIdx.x;                 // 256 threads
    __shared__ float red[8];

    // two contiguous float4 sweeps: elems [tid*4 .. tid*4+3] and [+1024 ..]
    float4 v0 = *(const float4*)(p + tid * 4);
    float4 v1 = *(const float4*)(p + 1024 + tid * 4);
    int4  q0 = *(const int4*)(mk + tid * 4);
    int4  q1 = *(const int4*)(mk + 1024 + tid * 4);

    float mx = -INFINITY;
    mx = q0.x ? fmaxf(mx, v0.x) : mx;  mx = q0.y ? fmaxf(mx, v0.y) : mx;
    mx = q0.z ? fmaxf(mx, v0.z) : mx;  mx = q0.w ? fmaxf(mx, v0.w) : mx;
    mx = q1.x ? fmaxf(mx, v1.x) : mx;  mx = q1.y ? fmaxf(mx, v1.y) : mx;
    mx = q1.z ? fmaxf(mx, v1.z) : mx;  mx = q1.w ? fmaxf(mx, v1.w) : mx;
    #pragma unroll
    for (int o = 16; o > 0; o >>= 1) mx = fmaxf(mx, __shfl_xor_sync(0xffffffffu, mx, o));
    if ((tid & 31) == 0) red[tid >> 5] = mx;
    __syncthreads();
    mx = red[0];
    #pragma unroll
    for (int i = 1; i < 8; i++) mx = fmaxf(mx, red[i]);
    __syncthreads();

    v0.x = q0.x ? __expf(v0.x - mx) : 0.0f;  v0.y = q0.y ? __expf(v0.y - mx) : 0.0f;
    v0.z = q0.z ? __expf(v0.z - mx) : 0.0f;  v0.w = q0.w ? __expf(v0.w - mx) : 0.0f;
    v1.x = q1.x ? __expf(v1.x - mx) : 0.0f;  v1.y = q1.y ? __expf(v1.y - mx) : 0.0f;
    v1.z = q1.z ? __expf(v1.z - mx) : 0.0f;  v1.w = q1.w ? __expf(v1.w - mx) : 0.0f;

    float s = v0.x + v0.y + v0.z + v0.w + v1.x + v1.y + v1.z + v1.w;
    #pragma unroll
    for (int o = 16; o > 0; o >>= 1) s += __shfl_xor_sync(0xffffffffu, s, o);
    if ((tid & 31) == 0) red[tid >> 5] = s;
    __syncthreads();
    float tot = red[0];
    #pragma unroll
    for (int i = 1; i < 8; i++) tot += red[i];
    const float inv = 1.0f / tot;

    v0.x *= inv; v0.y *= inv; v0.z *= inv; v0.w *= inv;
    v1.x *= inv; v1.y *= inv; v1.z *= inv; v1.w *= inv;
    *(float4*)(p + tid * 4) = v0;
    *(float4*)(p + 1024 + tid * 4) = v1;
}

// ---------------------------------------------------------------------------
// Kernel 4: out[b,m,d] = sum_n att[b,m,n]*key[b,n,d]  (NN, tf32 wmma)
// same structure: 128x128 tile, double buffer, register prefetch
// ---------------------------------------------------------------------------
__global__ __launch_bounds__(256)
void outgemm_kernel(const float* __restrict__ att, const float* __restrict__ key,
                    float* __restrict__ out) {
    extern __shared__ float sm[];
    float* As = sm;                       // [2][128][36]  (att, m-major)
    float* Bs = sm + 2 * A_STAGE;         // [2][32][132]  (key, k-major)

    const int b  = blockIdx.z;
    const int m0 = blockIdx.y * 128;
    const int n0 = blockIdx.x * 128;      // over DIM
    const int tid  = threadIdx.x;
    const int warp = tid >> 5;
    const int wm = warp >> 1, wn = warp & 1;

    const float* attb = att + (size_t)b * MQ * NKV;
    const float* keyb = key + (size_t)b * NKV * DIM;

    int arow[4], acol[4], brow[4], bcol[4];
    #pragma unroll
    for (int it = 0; it < 4; it++) {
        int idx = it * 256 + tid;
        arow[it] = idx >> 3;  acol[it] = (idx & 7) * 4;     // A: 128 x 32
        brow[it] = idx >> 5;  bcol[it] = (idx & 31) * 4;    // B: 32 x 128
    }

    wmma::fragment<wmma::accumulator, 16, 16, 8, float> c[2][4];
    #pragma unroll
    for (int i = 0; i < 2; i++)
        #pragma unroll
        for (int j = 0; j < 4; j++)
            wmma::fill_fragment(c[i][j], 0.0f);

    float4 ra[4], rb[4];
    #pragma unroll
    for (int it = 0; it < 4; it++) {
        ra[it] = *(const float4*)(attb + (size_t)(m0 + arow[it]) * NKV + acol[it]);
        rb[it] = *(const float4*)(keyb + (size_t)brow[it] * DIM + n0 + bcol[it]);
    }
    #pragma unroll
    for (int it = 0; it < 4; it++) {
        float4 va, vb;
        va.x = wmma::__float_to_tf32(ra[it].x); va.y = wmma::__float_to_tf32(ra[it].y);
        va.z = wmma::__float_to_tf32(ra[it].z); va.w = wmma::__float_to_tf32(ra[it].w);
        vb.x = wmma::__float_to_tf32(rb[it].x); vb.y = wmma::__float_to_tf32(rb[it].y);
        vb.z = wmma::__float_to_tf32(rb[it].z); vb.w = wmma::__float_to_tf32(rb[it].w);
        *(float4*)(As + arow[it] * LDA + acol[it]) = va;
        *(float4*)(Bs + brow[it] * LDB_NN + bcol[it]) = vb;
    }
    __syncthreads();

    const int NIT = NKV / 32;   // 64
    for (int t = 0; t < NIT; t++) {
        const int buf = t & 1;
        if (t + 1 < NIT) {
            const int k0 = (t + 1) * 32;
            #pragma unroll
            for (int it = 0; it < 4; it++) {
                ra[it] = *(const float4*)(attb + (size_t)(m0 + arow[it]) * NKV + k0 + acol[it]);
                rb[it] = *(const float4*)(keyb + (size_t)(k0 + brow[it]) * DIM + n0 + bcol[it]);
            }
        }
        const float* Ab = As + buf * A_STAGE;
        const float* Bb = Bs + buf * B_STAGE_NN;
        #pragma unroll
        for (int kk = 0; kk < 4; kk++) {
            wmma::fragment<wmma::matrix_a, 16, 16, 8, wmma::precision::tf32, wmma::row_major> a[2];
            wmma::fragment<wmma::matrix_b, 16, 16, 8, wmma::precision::tf32, wmma::row_major> bf[4];
            #pragma unroll
            for (int i = 0; i < 2; i++)
                wmma::load_matrix_sync(a[i], Ab + (wm * 32 + i * 16) * LDA + kk * 8, LDA);
            #pragma unroll
            for (int j = 0; j < 4; j++)
                wmma::load_matrix_sync(bf[j], Bb + (kk * 8) * LDB_NN + wn * 64 + j * 16, LDB_NN);
            #pragma unroll
            for (int i = 0; i < 2; i++)
                #pragma unroll
                for (int j = 0; j < 4; j++)
                    wmma::mma_sync(c[i][j], a[i], bf[j], c[i][j]);
        }
        if (t + 1 < NIT) {
            float* An = As + (buf ^ 1) * A_STAGE;
            float* Bn = Bs + (buf ^ 1) * B_STAGE_NN;
            #pragma unroll
            for (int it = 0; it < 4; it++) {
                float4 va, vb;
                va.x = wmma::__float_to_tf32(ra[it].x); va.y = wmma::__float_to_tf32(ra[it].y);
                va.z = wmma::__float_to_tf32(ra[it].z); va.w = wmma::__float_to_tf32(ra[it].w);
                vb.x = wmma::__float_to_tf32(rb[it].x); vb.y = wmma::__float_to_tf32(rb[it].y);
                vb.z = wmma::__float_to_tf32(rb[it].z); vb.w = wmma::__float_to_tf32(rb[it].w);
                *(float4*)(An + arow[it] * LDA + acol[it]) = va;
                *(float4*)(Bn + brow[it] * LDB_NN + bcol[it]) = vb;
            }
        }
        __syncthreads();
    }

    #pragma unroll
    for (int i = 0; i < 2; i++)
        #pragma unroll
        for (int j = 0; j < 4; j++) {
            float* p = out + ((size_t)b * MQ + m0 + wm * 32 + i * 16) * DIM
                           + n0 + wn * 64 + j * 16;
            wmma::store_matrix_sync(p, c[i][j], DIM, wmma::mem_row_major);
        }
}

// ---------------------------------------------------------------------------
extern "C" void kernel_launch(void* const* d_in, const int* in_sizes, int n_in,
                              void* d_out, int out_size) {
    const float* query = (const float*)d_in[0];
    const float* key   = (const float*)d_in[1];
    const float* W     = (const float*)d_in[2];
    const int*   mask  = (const int*)d_in[3];

    float* out = (float*)d_out;
    const long long need = (long long)NB * MQ * DIM + (long long)NB * MQ * NKV;
    float* att;
    if ((long long)out_size >= need) {
        att = out + (size_t)NB * MQ * DIM;
    } else {
        void* p = nullptr;
        cudaGetSymbolAddress(&p, g_att);
        att = (float*)p;
    }

    const int smem_logits = 2 * (A_STAGE + B_STAGE_NT) * sizeof(float);  // 73728
    const int smem_out    = 2 * (A_STAGE + B_STAGE_NN) * sizeof(float);  // 70656
    cudaFuncSetAttribute(logits_kernel, cudaFuncAttributeMaxDynamicSharedMemorySize, smem_logits);
    cudaFuncSetAttribute(outgemm_kernel, cudaFuncAttributeMaxDynamicSharedMemorySize, smem_out);

    {   // qW = query @ W / 32
        dim3 g(DIM / 64, MQ / 64);
        qw_kernel<<<g, 256>>>(query, W);
    }
    {   // raw logits -> att region
        dim3 g(NKV / 128, MQ / 128, NB);
        logits_kernel<<<g, 256, smem_logits>>>(key, att);
    }
    {   // masked softmax in place
        softmax_kernel<<<NB * MQ, 256>>>(mask, att);
    }
    {   // out = att @ key
        dim3 g(DIM / 128, MQ / 128, NB);
        outgemm_kernel<<<g, 256, smem_out>>>(att, key, out);
    }
}